// round 14
// baseline (speedup 1.0000x reference)
#include <cuda_runtime.h>
#include <cuda_fp16.h>
#include <cstdint>
#include <cstddef>

#define BB 8
#define NN 2048
#define DD 128

// ---------------- scratch (no allocs allowed) ----------------
__device__ __half g_a16[(size_t)BB * NN * NN];   // 67MB frag-packed fp16 A
__device__ __half g_zpk[BB * NN * DD];           // 4MB packed fp16 Z
__device__ float  g_part[2 * BB * NN * DD];      // split-K partials (16MB)
__device__ float  g_rs  [BB * NN];               // full rowsums (layer 0)
__device__ float  g_invden[BB * NN];

typedef unsigned long long u64;

// ---------------- PTX helpers ----------------
__device__ __forceinline__ uint32_t smem_u32(const void* p) {
    uint32_t a;
    asm("{ .reg .u64 t; cvta.to.shared.u64 t, %1; cvt.u32.u64 %0, t; }" : "=r"(a) : "l"(p));
    return a;
}
__device__ __forceinline__ void cp16(uint32_t dst, const void* src) {
    asm volatile("cp.async.cg.shared.global [%0], [%1], 16;" :: "r"(dst), "l"(src));
}
__device__ __forceinline__ void cp_commit() {
    asm volatile("cp.async.commit_group;" ::: "memory");
}
__device__ __forceinline__ uint32_t cvt_tf32(float x) {
    uint32_t r; asm("cvt.rna.tf32.f32 %0, %1;" : "=r"(r) : "f"(x)); return r;
}
__device__ __forceinline__ uint32_t pkh(float lo, float hi) {
    uint32_t d;
    asm("cvt.rn.f16x2.f32 %0, %1, %2;" : "=r"(d) : "f"(hi), "f"(lo));
    return d;
}
__device__ __forceinline__ void mma_tf32(float* d,
    uint32_t a0, uint32_t a1, uint32_t a2, uint32_t a3, uint32_t b0, uint32_t b1)
{
    asm volatile(
        "mma.sync.aligned.m16n8k8.row.col.f32.tf32.tf32.f32 "
        "{%0,%1,%2,%3}, {%4,%5,%6,%7}, {%8,%9}, {%0,%1,%2,%3};"
        : "+f"(d[0]), "+f"(d[1]), "+f"(d[2]), "+f"(d[3])
        : "r"(a0), "r"(a1), "r"(a2), "r"(a3), "r"(b0), "r"(b1));
}
__device__ __forceinline__ void mma_f16(float* d,
    uint32_t a0, uint32_t a1, uint32_t a2, uint32_t a3, uint32_t b0, uint32_t b1)
{
    asm volatile(
        "mma.sync.aligned.m16n8k16.row.col.f32.f16.f16.f32 "
        "{%0,%1,%2,%3}, {%4,%5,%6,%7}, {%8,%9}, {%0,%1,%2,%3};"
        : "+f"(d[0]), "+f"(d[1]), "+f"(d[2]), "+f"(d[3])
        : "r"(a0), "r"(a1), "r"(a2), "r"(a3), "r"(b0), "r"(b1));
}

// =================================================================
//  Layouts
//  A16 [b][ks16 0..127][row 0..2047][16 halves]: half p = c*4+h*2+e
//     holds k-offset kl = 2c+8h+e  ->  LDS.64 at c*8B = (a0pair, a2pair).
//  Zpk [b][kp=t/32 0..63][n 0..127][32 halves]: half = c*8 + ks*4 + h*2 + e
//     -> LDS.128 at n*64B + c*16B = {b0,b1 (ks0), b0,b1 (ks1)}.
// =================================================================

// =================================================================
//  a2h: streaming convert A fp32 -> frag-packed A16 + full rowsums.
// =================================================================
__global__ __launch_bounds__(256, 4) void a2h(
    const float* __restrict__ A,
    __half* __restrict__ A16,
    float* __restrict__ rsOut)
{
    __shared__ __align__(16) float sbuf[3][32][132];
    __shared__ float red[8][32];

    const int tid = threadIdx.x;
    const int b = blockIdx.y, row0 = blockIdx.x * 32;

    const int lrow = tid >> 3, lj = tid & 7;
    const float* src = A + ((size_t)b * NN + row0 + lrow) * NN + lj * 16;

    auto load = [&](int i) {
        const uint32_t d = smem_u32(&sbuf[i % 3][lrow][lj * 16]);
        const float* s = src + i * 128;
        cp16(d, s);  cp16(d + 16, s + 4);  cp16(d + 32, s + 8);  cp16(d + 48, s + 12);
        cp_commit();
    };

    const int ks = tid >> 5, row = tid & 31;
    float rsum = 0.f;

    load(0);
    load(1);

    #pragma unroll 1
    for (int i = 0; i < 16; i++) {
        if (i < 14) { asm volatile("cp.async.wait_group 1;" ::: "memory"); }
        else        { asm volatile("cp.async.wait_group 0;" ::: "memory"); }
        __syncthreads();
        if (i < 14) load(i + 2);

        const float* r = &sbuf[i % 3][row][ks * 16];
        float4 v0 = reinterpret_cast<const float4*>(r)[0];
        float4 v1 = reinterpret_cast<const float4*>(r)[1];
        float4 v2 = reinterpret_cast<const float4*>(r)[2];
        float4 v3 = reinterpret_cast<const float4*>(r)[3];
        rsum += (v0.x + v0.y + v0.z + v0.w) + (v1.x + v1.y + v1.z + v1.w)
              + (v2.x + v2.y + v2.z + v2.w) + (v3.x + v3.y + v3.z + v3.w);
        uint4 w0, w1;
        w0.x = pkh(v0.x, v0.y);  w0.y = pkh(v2.x, v2.y);
        w0.z = pkh(v0.z, v0.w);  w0.w = pkh(v2.z, v2.w);
        w1.x = pkh(v1.x, v1.y);  w1.y = pkh(v3.x, v3.y);
        w1.z = pkh(v1.z, v1.w);  w1.w = pkh(v3.z, v3.w);
        uint4* dst = reinterpret_cast<uint4*>(
            A16 + ((size_t)(b * 128 + i * 8 + ks) * NN + row0 + row) * 16);
        dst[0] = w0;  dst[1] = w1;
    }

    red[ks][row] = rsum;
    __syncthreads();
    if (tid < 32) {
        float s = 0.f;
        #pragma unroll
        for (int q = 0; q < 8; q++) s += red[q][tid];
        rsOut[(size_t)b * NN + row0 + tid] = s;
    }
}

// =================================================================
//  ax_rest: A16 @ Z (all 3 layers). 4 warps, warp tile 64x64,
//  BK=32, 16KB stages x4, occ 2, split-K x2. 128 threads.
//  LDS redundancy: A 2x, B 2x (was A 2x, B 4x at 8 warps).
// =================================================================
#define STB12 16384
#define SMEM_AX12 (1024 + 4 * STB12)   // 66560
#define NCH12 32

__global__ __launch_bounds__(128, 2) void ax_rest(
    const __half* __restrict__ A16, const __half* __restrict__ Zp,
    float* __restrict__ Pout)
{
    extern __shared__ __align__(16) char sm[];
    const uint32_t smb = smem_u32(sm);
    const int tid = threadIdx.x, lane = tid & 31, wid = tid >> 5;
    const int b = blockIdx.y, z = blockIdx.z, m0 = blockIdx.x * 128;

    // loader mapping (128 threads, 8 cp16 each = 16KB/chunk)
    const int aks = tid >> 6;                 // which ks16 block (0/1)
    const int aidx = tid & 63;                // 64B unit within 4KB block (2 rows)
    const __half* aBase = A16 + ((size_t)(b * 128 + z * 64 + aks) * NN + m0 + 2 * aidx) * 16;
    const __half* zBase = Zp + (size_t)b * NN * DD + (size_t)(z * 32) * 4096 + tid * 32;
    const uint32_t adst = (uint32_t)(aks * 4096 + aidx * 64);
    const uint32_t zdst = (uint32_t)(8192 + tid * 64);

    auto load_chunk = [&](int i) {
        const uint32_t base = smb + 1024 + (i & 3) * STB12;
        const __half* sa = aBase + (size_t)(2 * i) * NN * 16;
        const uint32_t da = base + adst;
        cp16(da, sa);       cp16(da + 16, sa + 8);
        cp16(da + 32, sa + 16);  cp16(da + 48, sa + 24);
        const __half* sz = zBase + (size_t)i * 4096;
        const uint32_t dz = base + zdst;
        cp16(dz, sz);       cp16(dz + 16, sz + 8);
        cp16(dz + 32, sz + 16);  cp16(dz + 48, sz + 24);
        cp_commit();
    };

    // compute mapping: warp grid 2(M) x 2(N), warp tile 64x64
    const int g = lane >> 2, c = lane & 3;
    const int wm = (wid & 1) * 64, wn = (wid >> 1) * 64;

    float acc[4][8][4];
    #pragma unroll
    for (int mi = 0; mi < 4; mi++)
        #pragma unroll
        for (int nj = 0; nj < 8; nj++)
            #pragma unroll
            for (int q = 0; q < 4; q++) acc[mi][nj][q] = 0.f;

    load_chunk(0);
    load_chunk(1);
    load_chunk(2);

    #pragma unroll 1
    for (int i = 0; i < NCH12; i++) {
        if (i < NCH12 - 2)       { asm volatile("cp.async.wait_group 2;" ::: "memory"); }
        else if (i == NCH12 - 2) { asm volatile("cp.async.wait_group 1;" ::: "memory"); }
        else                     { asm volatile("cp.async.wait_group 0;" ::: "memory"); }
        __syncthreads();
        if (i < NCH12 - 3) load_chunk(i + 3);

        const __half* As = reinterpret_cast<const __half*>(sm + 1024 + (i & 3) * STB12);
        const __half* Bs = As + 4096;          // +8192 bytes

        // A fragments: 4 m16 tiles x 2 ks16 -> 16 LDS.64
        uint32_t af[2][4][4];
        #pragma unroll
        for (int ks2 = 0; ks2 < 2; ks2++)
            #pragma unroll
            for (int mi = 0; mi < 4; mi++) {
                const int rlo = wm + 16 * mi + g;
                uint2 u = *reinterpret_cast<const uint2*>(As + ks2 * 2048 + rlo * 16 + c * 4);
                uint2 v = *reinterpret_cast<const uint2*>(As + ks2 * 2048 + (rlo + 8) * 16 + c * 4);
                af[ks2][mi][0] = u.x;  af[ks2][mi][1] = v.x;
                af[ks2][mi][2] = u.y;  af[ks2][mi][3] = v.y;
            }
        // B fragments + MMAs: 8 n8 tiles, one LDS.128 each covering both ks
        #pragma unroll
        for (int nj = 0; nj < 8; nj++) {
            const int col = wn + 8 * nj + g;
            uint4 bb = *reinterpret_cast<const uint4*>(Bs + col * 32 + c * 8);
            #pragma unroll
            for (int mi = 0; mi < 4; mi++) {
                mma_f16(acc[mi][nj], af[0][mi][0], af[0][mi][1], af[0][mi][2], af[0][mi][3], bb.x, bb.y);
                mma_f16(acc[mi][nj], af[1][mi][0], af[1][mi][1], af[1][mi][2], af[1][mi][3], bb.z, bb.w);
            }
        }
    }

    float* pb = Pout + (size_t)(z * BB + b) * NN * DD;
    #pragma unroll
    for (int mi = 0; mi < 4; mi++) {
        const int r_lo = wm + 16 * mi + g;
        float* o_lo = pb + (size_t)(m0 + r_lo) * DD;
        float* o_hi = pb + (size_t)(m0 + r_lo + 8) * DD;
        #pragma unroll
        for (int nj = 0; nj < 8; nj++) {
            const int col = wn + 8 * nj + 2 * c;
            *reinterpret_cast<float2*>(o_lo + col) = make_float2(acc[mi][nj][0], acc[mi][nj][1]);
            *reinterpret_cast<float2*>(o_hi + col) = make_float2(acc[mi][nj][2], acc[mi][nj][3]);
        }
    }
}

// =================================================================
//  Z-pack epilogue helper (shared by zk_t and fused_rz)
// =================================================================
__device__ __forceinline__ void zpack_store(
    __half* hb, const float acc[2][8][4],
    int wm, int wn, int g, int c)
{
    #pragma unroll
    for (int mi = 0; mi < 2; mi++)
        #pragma unroll
        for (int q = 0; q < 4; q++)
            #pragma unroll
            for (int nj = 0; nj < 8; nj++) {
                const int t = wm + 16 * mi + g + 8 * (q >> 1);
                const int n = wn + 8 * nj + 2 * c + (q & 1);
                const int kl = t & 15, e = kl & 1, xx = kl >> 1;
                const int idx = (t >> 5) * 4096 + n * 32
                              + (xx & 3) * 8 + ((t >> 4) & 1) * 4 + (xx >> 2) * 2 + e;
                hb[idx] = __float2half(acc[mi][nj][q]);
            }
}

// =================================================================
//  zk_t (layer 0): Z = X @ W0, tf32 mainloop, packed-fp16 epilogue.
// =================================================================
#define APAD_ZK 36
#define WPAD   136
#define AZ_TB (128 * APAD_ZK * 4)     // 18432
#define W_TB  (32 * WPAD * 4)         // 17408
#define STB_ZK (AZ_TB + W_TB)
#define SMEM_ZK (1024 + 3 * STB_ZK)   // 108544

__global__ __launch_bounds__(256, 2) void zk_t(
    const float* __restrict__ X,
    const float* __restrict__ W,
    __half* __restrict__ Zp)
{
    extern __shared__ __align__(16) char sm[];
    const uint32_t smb = smem_u32(sm);
    const int tid = threadIdx.x, lane = tid & 31, wid = tid >> 5;
    const int m0 = blockIdx.x * 128;

    const int arow = tid >> 1, ahalf = tid & 1;
    const float* aGlob = X + (size_t)(m0 + arow) * DD + ahalf * 16;
    const uint32_t adst = (uint32_t)(arow * (APAD_ZK * 4) + ahalf * 64);
    const int wkr = tid >> 3, wkc = (tid & 7) * 16;
    const float* wGlob = W + (size_t)wkr * DD + wkc;
    const uint32_t wdst = (uint32_t)(AZ_TB + wkr * (WPAD * 4) + wkc * 4);

    auto load_chunk = [&](int i) {
        const uint32_t base = smb + 1024 + (i % 3) * STB_ZK;
        const float* sa = aGlob + i * 32;
        const uint32_t da = base + adst;
        cp16(da,      sa);      cp16(da + 16, sa + 4);
        cp16(da + 32, sa + 8);  cp16(da + 48, sa + 12);
        const float* sw = wGlob + (size_t)i * 32 * DD;
        const uint32_t dw = base + wdst;
        cp16(dw,      sw);      cp16(dw + 16, sw + 4);
        cp16(dw + 32, sw + 8);  cp16(dw + 48, sw + 12);
        cp_commit();
    };

    const int g = lane >> 2, c = lane & 3;
    const int wm = (wid & 3) * 32, wn = (wid >> 2) * 64;

    float acc[2][8][4];
    #pragma unroll
    for (int mi = 0; mi < 2; mi++)
        #pragma unroll
        for (int nj = 0; nj < 8; nj++)
            #pragma unroll
            for (int q = 0; q < 4; q++) acc[mi][nj][q] = 0.f;

    load_chunk(0);
    load_chunk(1);

    #pragma unroll 1
    for (int i = 0; i < 4; i++) {
        if (i < 2) { asm volatile("cp.async.wait_group 1;" ::: "memory"); }
        else       { asm volatile("cp.async.wait_group 0;" ::: "memory"); }
        __syncthreads();
        if (i < 2) load_chunk(i + 2);

        const float* As = reinterpret_cast<const float*>(sm + 1024 + (i % 3) * STB_ZK);
        const uint32_t* Wu = reinterpret_cast<const uint32_t*>(As + AZ_TB / 4);

        #pragma unroll
        for (int ks = 0; ks < 4; ks++) {
            const int kk = ks * 8 + c;
            uint32_t a0[4], a1[4];
            a0[0] = cvt_tf32(As[(wm + g)      * APAD_ZK + kk]);
            a0[1] = cvt_tf32(As[(wm + g + 8)  * APAD_ZK + kk]);
            a0[2] = cvt_tf32(As[(wm + g)      * APAD_ZK + kk + 4]);
            a0[3] = cvt_tf32(As[(wm + g + 8)  * APAD_ZK + kk + 4]);
            a1[0] = cvt_tf32(As[(wm + 16 + g) * APAD_ZK + kk]);
            a1[1] = cvt_tf32(As[(wm + 24 + g) * APAD_ZK + kk]);
            a1[2] = cvt_tf32(As[(wm + 16 + g) * APAD_ZK + kk + 4]);
            a1[3] = cvt_tf32(As[(wm + 24 + g) * APAD_ZK + kk + 4]);
            #pragma unroll
            for (int nj = 0; nj < 8; nj++) {
                const int col = wn + 8 * nj + g;
                uint32_t b0 = cvt_tf32(__uint_as_float(Wu[kk       * WPAD + col]));
                uint32_t b1 = cvt_tf32(__uint_as_float(Wu[(kk + 4) * WPAD + col]));
                mma_tf32(acc[0][nj], a0[0], a0[1], a0[2], a0[3], b0, b1);
                mma_tf32(acc[1][nj], a1[0], a1[1], a1[2], a1[3], b0, b1);
            }
        }
    }

    __syncthreads();
    __half* hb = reinterpret_cast<__half*>(sm + 1024);
    zpack_store(hb, acc, wm, wn, g, c);
    __syncthreads();

    const int zb = m0 >> 11, mloc = m0 & 2047;
    uint4* dst = reinterpret_cast<uint4*>(Zp + (size_t)zb * NN * DD + (size_t)(mloc >> 5) * 4096);
    const uint4* src = reinterpret_cast<const uint4*>(hb);
    #pragma unroll 1
    for (int i2 = tid; i2 < 2048; i2 += 256)
        dst[i2] = src[i2];
}

// =================================================================
//  fused_rz: x = relu((p0+p1+bias)*invden) (never materialized),
//  then Z = x @ W (whole W in smem), packed-fp16 out. occ 1.
// =================================================================
#define APAD_FZ 132
#define FX_TB (128 * APAD_FZ * 4)             // 67584
#define FW_OFF (1024 + FX_TB)                 // 68608
#define SMEM_FZ (FW_OFF + 128 * WPAD * 4)     // 138240

template<bool FIRST>
__global__ __launch_bounds__(256, 1) void fused_rz(
    const float* __restrict__ part,
    const float* __restrict__ rs,
    float* __restrict__ invd,
    const float* __restrict__ bias,
    const float* __restrict__ W,
    __half* __restrict__ Zp)
{
    extern __shared__ __align__(16) char sm[];
    const uint32_t smb = smem_u32(sm);
    const int tid = threadIdx.x, lane = tid & 31, wid = tid >> 5;
    const int m0 = blockIdx.x * 128;

    {
        const int k = tid >> 1, nh = tid & 1;
        const float* wsrc = W + (size_t)k * DD + nh * 64;
        const uint32_t wdst = smb + FW_OFF + (uint32_t)(k * WPAD + nh * 64) * 4;
        #pragma unroll
        for (int j = 0; j < 16; j++) cp16(wdst + j * 16, wsrc + j * 4);
        cp_commit();
    }

    float* As = reinterpret_cast<float*>(sm + 1024);
    {
        const int tr = tid >> 1, fh = (tid & 1) * 64;
        const size_t tok = (size_t)(m0 + tr);
        float inv;
        if (FIRST) {
            inv = 1.0f / (rs[tok] + 1.0f);
            if ((tid & 1) == 0) invd[tok] = inv;
        } else {
            inv = invd[tok];
        }
        const float4* p0 = reinterpret_cast<const float4*>(part + tok * DD + fh);
        const float4* p1 = reinterpret_cast<const float4*>(part + (size_t)BB * NN * DD + tok * DD + fh);
        #pragma unroll
        for (int j = 0; j < 16; j++) {
            float4 a = p0[j], b2 = p1[j];
            float4 bv = *reinterpret_cast<const float4*>(bias + fh + j * 4);
            float4 o;
            o.x = fmaxf((a.x + b2.x + bv.x) * inv, 0.f);
            o.y = fmaxf((a.y + b2.y + bv.y) * inv, 0.f);
            o.z = fmaxf((a.z + b2.z + bv.z) * inv, 0.f);
            o.w = fmaxf((a.w + b2.w + bv.w) * inv, 0.f);
            *reinterpret_cast<float4*>(As + tr * APAD_FZ + fh + j * 4) = o;
        }
    }
    asm volatile("cp.async.wait_group 0;" ::: "memory");
    __syncthreads();

    const int g = lane >> 2, c = lane & 3;
    const int wm = (wid & 3) * 32, wn = (wid >> 2) * 64;
    const uint32_t* Wu = reinterpret_cast<const uint32_t*>(sm + FW_OFF);

    float acc[2][8][4];
    #pragma unroll
    for (int mi = 0; mi < 2; mi++)
        #pragma unroll
        for (int nj = 0; nj < 8; nj++)
            #pragma unroll
            for (int q = 0; q < 4; q++) acc[mi][nj][q] = 0.f;

    #pragma unroll 1
    for (int ks8 = 0; ks8 < 16; ks8++) {
        const int kk = ks8 * 8 + c;
        uint32_t a0[4], a1[4];
        a0[0] = cvt_tf32(As[(wm + g)      * APAD_FZ + kk]);
        a0[1] = cvt_tf32(As[(wm + g + 8)  * APAD_FZ + kk]);
        a0[2] = cvt_tf32(As[(wm + g)      * APAD_FZ + kk + 4]);
        a0[3] = cvt_tf32(As[(wm + g + 8)  * APAD_FZ + kk + 4]);
        a1[0] = cvt_tf32(As[(wm + 16 + g) * APAD_FZ + kk]);
        a1[1] = cvt_tf32(As[(wm + 24 + g) * APAD_FZ + kk]);
        a1[2] = cvt_tf32(As[(wm + 16 + g) * APAD_FZ + kk + 4]);
        a1[3] = cvt_tf32(As[(wm + 24 + g) * APAD_FZ + kk + 4]);
        #pragma unroll
        for (int nj = 0; nj < 8; nj++) {
            const int col = wn + 8 * nj + g;
            uint32_t b0 = cvt_tf32(__uint_as_float(Wu[kk       * WPAD + col]));
            uint32_t b1 = cvt_tf32(__uint_as_float(Wu[(kk + 4) * WPAD + col]));
            mma_tf32(acc[0][nj], a0[0], a0[1], a0[2], a0[3], b0, b1);
            mma_tf32(acc[1][nj], a1[0], a1[1], a1[2], a1[3], b0, b1);
        }
    }

    __syncthreads();
    __half* hb = reinterpret_cast<__half*>(sm + 1024);
    zpack_store(hb, acc, wm, wn, g, c);
    __syncthreads();

    const int zb = m0 >> 11, mloc = m0 & 2047;
    uint4* dst = reinterpret_cast<uint4*>(Zp + (size_t)zb * NN * DD + (size_t)(mloc >> 5) * 4096);
    const uint4* src = reinterpret_cast<const uint4*>(hb);
    #pragma unroll 1
    for (int i2 = tid; i2 < 2048; i2 += 256)
        dst[i2] = src[i2];
}

// =================================================================
//  Final reduce: out = relu((p0 + p1 + bias) * invden)
// =================================================================
__global__ __launch_bounds__(256, 8) void reduce_fin(
    const float* __restrict__ part,
    const float* __restrict__ bias,
    const float* __restrict__ invd,
    float* __restrict__ out)
{
    const size_t base = ((size_t)blockIdx.x * 256 + threadIdx.x) * 4;
    const int f0 = (int)(base & 127);
    const size_t tg = base >> 7;
    const float inv = invd[tg];

    float4 p0 = *reinterpret_cast<const float4*>(part + base);
    float4 p1 = *reinterpret_cast<const float4*>(part + (size_t)BB * NN * DD + base);
    float4 bv = *reinterpret_cast<const float4*>(bias + f0);
    float4 o;
    o.x = fmaxf((p0.x + p1.x + bv.x) * inv, 0.f);
    o.y = fmaxf((p0.y + p1.y + bv.y) * inv, 0.f);
    o.z = fmaxf((p0.z + p1.z + bv.z) * inv, 0.f);
    o.w = fmaxf((p0.w + p1.w + bv.w) * inv, 0.f);
    *reinterpret_cast<float4*>(out + base) = o;
}

// =================================================================
extern "C" void kernel_launch(void* const* d_in, const int* in_sizes, int n_in,
                              void* d_out, int out_size)
{
    const float *inputs = nullptr, *adj = nullptr, *W = nullptr, *bias = nullptr;
    for (int i = 0; i < n_in; i++) {
        const long long s = in_sizes[i];
        if      (s == (long long)BB * NN * DD) inputs = (const float*)d_in[i];
        else if (s == (long long)BB * NN * NN) adj    = (const float*)d_in[i];
        else if (s == 3LL * DD * DD)           W      = (const float*)d_in[i];
        else if (s == 3LL * DD)                bias   = (const float*)d_in[i];
    }
    float* out = (float*)d_out;

    __half *a16, *zp;
    float *part, *rsv, *invd;
    cudaGetSymbolAddress((void**)&a16,  g_a16);
    cudaGetSymbolAddress((void**)&zp,   g_zpk);
    cudaGetSymbolAddress((void**)&part, g_part);
    cudaGetSymbolAddress((void**)&rsv,  g_rs);
    cudaGetSymbolAddress((void**)&invd, g_invden);

    static bool attr_done = false;
    if (!attr_done) {
        cudaFuncSetAttribute(ax_rest,         cudaFuncAttributeMaxDynamicSharedMemorySize, SMEM_AX12);
        cudaFuncSetAttribute(zk_t,            cudaFuncAttributeMaxDynamicSharedMemorySize, SMEM_ZK);
        cudaFuncSetAttribute(fused_rz<true>,  cudaFuncAttributeMaxDynamicSharedMemorySize, SMEM_FZ);
        cudaFuncSetAttribute(fused_rz<false>, cudaFuncAttributeMaxDynamicSharedMemorySize, SMEM_FZ);
        attr_done = true;
    }

    const dim3 gAX(NN / 128, BB, 2);          // 256 CTAs (split-K x2), 128 thr
    const dim3 gA2H(NN / 32, BB);             // 512 CTAs
    const int  gZ = (BB * NN) / 128;          // 128 CTAs
    const int  gRED = (BB * NN * DD) / 1024;  // 2048 CTAs

    // layer 0
    zk_t<<<gZ, 256, SMEM_ZK>>>(inputs, W, zp);
    a2h<<<gA2H, 256>>>(adj, a16, rsv);
    ax_rest<<<gAX, 128, SMEM_AX12>>>(a16, zp, part);
    // reduce0 + zk1
    fused_rz<true ><<<gZ, 256, SMEM_FZ>>>(part, rsv, invd, bias, W + DD * DD, zp);
    // layer 1
    ax_rest<<<gAX, 128, SMEM_AX12>>>(a16, zp, part);
    // reduce1 + zk2
    fused_rz<false><<<gZ, 256, SMEM_FZ>>>(part, nullptr, invd, bias + DD, W + 2 * DD * DD, zp);
    // layer 2
    ax_rest<<<gAX, 128, SMEM_AX12>>>(a16, zp, part);
    reduce_fin<<<gRED, 256>>>(part, bias + 2 * DD, invd, out);
}

// round 16
// speedup vs baseline: 1.1106x; 1.1106x over previous
#include <cuda_runtime.h>
#include <cuda_fp16.h>
#include <cstdint>
#include <cstddef>

#define BB 8
#define NN 2048
#define DD 128

// ---------------- scratch (no allocs allowed) ----------------
__device__ __half g_a16[(size_t)BB * NN * NN];   // 67MB frag-packed fp16 A
__device__ __half g_zpk[BB * NN * DD];           // 4MB packed fp16 Z
__device__ float  g_part[2 * BB * NN * DD];      // split-K partials (16MB)
__device__ float  g_rs  [BB * NN];               // full rowsums (layer 0)
__device__ float  g_invden[BB * NN];

typedef unsigned long long u64;

// ---------------- PTX helpers ----------------
__device__ __forceinline__ uint32_t smem_u32(const void* p) {
    uint32_t a;
    asm("{ .reg .u64 t; cvta.to.shared.u64 t, %1; cvt.u32.u64 %0, t; }" : "=r"(a) : "l"(p));
    return a;
}
__device__ __forceinline__ void cp16(uint32_t dst, const void* src) {
    asm volatile("cp.async.cg.shared.global [%0], [%1], 16;" :: "r"(dst), "l"(src));
}
__device__ __forceinline__ void cp_commit() {
    asm volatile("cp.async.commit_group;" ::: "memory");
}
__device__ __forceinline__ uint32_t cvt_tf32(float x) {
    uint32_t r; asm("cvt.rna.tf32.f32 %0, %1;" : "=r"(r) : "f"(x)); return r;
}
__device__ __forceinline__ uint32_t pkh(float lo, float hi) {
    uint32_t d;
    asm("cvt.rn.f16x2.f32 %0, %1, %2;" : "=r"(d) : "f"(hi), "f"(lo));
    return d;
}
__device__ __forceinline__ void mma_tf32(float* d,
    uint32_t a0, uint32_t a1, uint32_t a2, uint32_t a3, uint32_t b0, uint32_t b1)
{
    asm volatile(
        "mma.sync.aligned.m16n8k8.row.col.f32.tf32.tf32.f32 "
        "{%0,%1,%2,%3}, {%4,%5,%6,%7}, {%8,%9}, {%0,%1,%2,%3};"
        : "+f"(d[0]), "+f"(d[1]), "+f"(d[2]), "+f"(d[3])
        : "r"(a0), "r"(a1), "r"(a2), "r"(a3), "r"(b0), "r"(b1));
}
__device__ __forceinline__ void mma_f16(float* d,
    uint32_t a0, uint32_t a1, uint32_t a2, uint32_t a3, uint32_t b0, uint32_t b1)
{
    asm volatile(
        "mma.sync.aligned.m16n8k16.row.col.f32.f16.f16.f32 "
        "{%0,%1,%2,%3}, {%4,%5,%6,%7}, {%8,%9}, {%0,%1,%2,%3};"
        : "+f"(d[0]), "+f"(d[1]), "+f"(d[2]), "+f"(d[3])
        : "r"(a0), "r"(a1), "r"(a2), "r"(a3), "r"(b0), "r"(b1));
}

// =================================================================
//  Layouts
//  A16 [b][ks16 0..127][row 0..2047][16 halves]: half p = c*4+h*2+e
//     holds k-offset kl = 2c+8h+e  ->  LDG.64 at c*8B = (a0pair, a2pair).
//  Zpk [b][kp=t/32 0..63][n 0..127][32 halves]: half = c*8 + ks*4 + h*2 + e
//     -> LDG.128 at n*64B + c*16B = {b0,b1 (ks0), b0,b1 (ks1)}.
// =================================================================

// =================================================================
//  a2h: streaming convert A fp32 -> frag-packed A16 + full rowsums.
// =================================================================
__global__ __launch_bounds__(256, 4) void a2h(
    const float* __restrict__ A,
    __half* __restrict__ A16,
    float* __restrict__ rsOut)
{
    __shared__ __align__(16) float sbuf[3][32][132];
    __shared__ float red[8][32];

    const int tid = threadIdx.x;
    const int b = blockIdx.y, row0 = blockIdx.x * 32;

    const int lrow = tid >> 3, lj = tid & 7;
    const float* src = A + ((size_t)b * NN + row0 + lrow) * NN + lj * 16;

    auto load = [&](int i) {
        const uint32_t d = smem_u32(&sbuf[i % 3][lrow][lj * 16]);
        const float* s = src + i * 128;
        cp16(d, s);  cp16(d + 16, s + 4);  cp16(d + 32, s + 8);  cp16(d + 48, s + 12);
        cp_commit();
    };

    const int ks = tid >> 5, row = tid & 31;
    float rsum = 0.f;

    load(0);
    load(1);

    #pragma unroll 1
    for (int i = 0; i < 16; i++) {
        if (i < 14) { asm volatile("cp.async.wait_group 1;" ::: "memory"); }
        else        { asm volatile("cp.async.wait_group 0;" ::: "memory"); }
        __syncthreads();
        if (i < 14) load(i + 2);

        const float* r = &sbuf[i % 3][row][ks * 16];
        float4 v0 = reinterpret_cast<const float4*>(r)[0];
        float4 v1 = reinterpret_cast<const float4*>(r)[1];
        float4 v2 = reinterpret_cast<const float4*>(r)[2];
        float4 v3 = reinterpret_cast<const float4*>(r)[3];
        rsum += (v0.x + v0.y + v0.z + v0.w) + (v1.x + v1.y + v1.z + v1.w)
              + (v2.x + v2.y + v2.z + v2.w) + (v3.x + v3.y + v3.z + v3.w);
        uint4 w0, w1;
        w0.x = pkh(v0.x, v0.y);  w0.y = pkh(v2.x, v2.y);
        w0.z = pkh(v0.z, v0.w);  w0.w = pkh(v2.z, v2.w);
        w1.x = pkh(v1.x, v1.y);  w1.y = pkh(v3.x, v3.y);
        w1.z = pkh(v1.z, v1.w);  w1.w = pkh(v3.z, v3.w);
        uint4* dst = reinterpret_cast<uint4*>(
            A16 + ((size_t)(b * 128 + i * 8 + ks) * NN + row0 + row) * 16);
        dst[0] = w0;  dst[1] = w1;
    }

    red[ks][row] = rsum;
    __syncthreads();
    if (tid < 32) {
        float s = 0.f;
        #pragma unroll
        for (int q = 0; q < 8; q++) s += red[q][tid];
        rsOut[(size_t)b * NN + row0 + tid] = s;
    }
}

// =================================================================
//  ax_direct: A16 @ Z, all fragments loaded DIRECTLY from global
//  (no smem, no syncthreads, no cp.async in mainloop).
//  CTA 128x128, 8 warps (warp grid 4Mx2N, tile 32x64), split-K x2.
//  Per warp per kp (32 tokens): 8 LDG.64 (A) + 8 LDG.128 (Z) + 32 HMMA.
// =================================================================
__global__ __launch_bounds__(256, 2) void ax_direct(
    const __half* __restrict__ A16, const __half* __restrict__ Zp,
    float* __restrict__ Pout)
{
    const int tid = threadIdx.x, lane = tid & 31, wid = tid >> 5;
    const int b = blockIdx.y, z = blockIdx.z, m0 = blockIdx.x * 128;
    const int g = lane >> 2, c = lane & 3;
    const int wm = (wid & 3) * 32, wn = (wid >> 2) * 64;

    // per-warp/lane base pointers (half-indexed)
    const __half* aBase = A16 + (size_t)(b * 128 + z * 64) * ((size_t)NN * 16)
                        + (size_t)(m0 + wm + g) * 16 + c * 4;
    const __half* zBase = Zp + (size_t)b * NN * DD + (size_t)(z * 32) * 4096
                        + (wn + g) * 32 + c * 8;

    float acc[2][8][4];
    #pragma unroll
    for (int mi = 0; mi < 2; mi++)
        #pragma unroll
        for (int nj = 0; nj < 8; nj++)
            #pragma unroll
            for (int q = 0; q < 4; q++) acc[mi][nj][q] = 0.f;

    #pragma unroll 1
    for (int kp = 0; kp < 32; kp++) {
        const __half* a0p = aBase + (size_t)(2 * kp) * ((size_t)NN * 16);
        const __half* a1p = a0p + (size_t)NN * 16;
        // A fragments: ks0/ks1 x mi0/mi1, rows (wm+16mi+g, +8)
        uint2 u00 = *reinterpret_cast<const uint2*>(a0p);
        uint2 v00 = *reinterpret_cast<const uint2*>(a0p + 8 * 16);
        uint2 u01 = *reinterpret_cast<const uint2*>(a0p + 16 * 16);
        uint2 v01 = *reinterpret_cast<const uint2*>(a0p + 24 * 16);
        uint2 u10 = *reinterpret_cast<const uint2*>(a1p);
        uint2 v10 = *reinterpret_cast<const uint2*>(a1p + 8 * 16);
        uint2 u11 = *reinterpret_cast<const uint2*>(a1p + 16 * 16);
        uint2 v11 = *reinterpret_cast<const uint2*>(a1p + 24 * 16);
        // Z fragments: one LDG.128 per n8 tile covers both ks16 halves
        const __half* zp2 = zBase + (size_t)kp * 4096;
        uint4 bb[8];
        #pragma unroll
        for (int nj = 0; nj < 8; nj++)
            bb[nj] = *reinterpret_cast<const uint4*>(zp2 + nj * 256);

        #pragma unroll
        for (int nj = 0; nj < 8; nj++) {
            mma_f16(acc[0][nj], u00.x, v00.x, u00.y, v00.y, bb[nj].x, bb[nj].y);
            mma_f16(acc[1][nj], u01.x, v01.x, u01.y, v01.y, bb[nj].x, bb[nj].y);
            mma_f16(acc[0][nj], u10.x, v10.x, u10.y, v10.y, bb[nj].z, bb[nj].w);
            mma_f16(acc[1][nj], u11.x, v11.x, u11.y, v11.y, bb[nj].z, bb[nj].w);
        }
    }

    float* pb = Pout + (size_t)(z * BB + b) * NN * DD;
    #pragma unroll
    for (int mi = 0; mi < 2; mi++) {
        const int r_lo = wm + 16 * mi + g;
        float* o_lo = pb + (size_t)(m0 + r_lo) * DD;
        float* o_hi = pb + (size_t)(m0 + r_lo + 8) * DD;
        #pragma unroll
        for (int nj = 0; nj < 8; nj++) {
            const int col = wn + 8 * nj + 2 * c;
            *reinterpret_cast<float2*>(o_lo + col) = make_float2(acc[mi][nj][0], acc[mi][nj][1]);
            *reinterpret_cast<float2*>(o_hi + col) = make_float2(acc[mi][nj][2], acc[mi][nj][3]);
        }
    }
}

// =================================================================
//  Z-pack epilogue helper (shared by zk_t and fused_rz)
// =================================================================
__device__ __forceinline__ void zpack_store(
    __half* hb, const float acc[2][8][4],
    int wm, int wn, int g, int c)
{
    #pragma unroll
    for (int mi = 0; mi < 2; mi++)
        #pragma unroll
        for (int q = 0; q < 4; q++)
            #pragma unroll
            for (int nj = 0; nj < 8; nj++) {
                const int t = wm + 16 * mi + g + 8 * (q >> 1);
                const int n = wn + 8 * nj + 2 * c + (q & 1);
                const int kl = t & 15, e = kl & 1, xx = kl >> 1;
                const int idx = (t >> 5) * 4096 + n * 32
                              + (xx & 3) * 8 + ((t >> 4) & 1) * 4 + (xx >> 2) * 2 + e;
                hb[idx] = __float2half(acc[mi][nj][q]);
            }
}

// =================================================================
//  zk_t (layer 0): Z = X @ W0, tf32 mainloop, packed-fp16 epilogue.
// =================================================================
#define APAD_ZK 36
#define WPAD   136
#define AZ_TB (128 * APAD_ZK * 4)     // 18432
#define W_TB  (32 * WPAD * 4)         // 17408
#define STB_ZK (AZ_TB + W_TB)
#define SMEM_ZK (1024 + 3 * STB_ZK)   // 108544

__global__ __launch_bounds__(256, 2) void zk_t(
    const float* __restrict__ X,
    const float* __restrict__ W,
    __half* __restrict__ Zp)
{
    extern __shared__ __align__(16) char sm[];
    const uint32_t smb = smem_u32(sm);
    const int tid = threadIdx.x, lane = tid & 31, wid = tid >> 5;
    const int m0 = blockIdx.x * 128;

    const int arow = tid >> 1, ahalf = tid & 1;
    const float* aGlob = X + (size_t)(m0 + arow) * DD + ahalf * 16;
    const uint32_t adst = (uint32_t)(arow * (APAD_ZK * 4) + ahalf * 64);
    const int wkr = tid >> 3, wkc = (tid & 7) * 16;
    const float* wGlob = W + (size_t)wkr * DD + wkc;
    const uint32_t wdst = (uint32_t)(AZ_TB + wkr * (WPAD * 4) + wkc * 4);

    auto load_chunk = [&](int i) {
        const uint32_t base = smb + 1024 + (i % 3) * STB_ZK;
        const float* sa = aGlob + i * 32;
        const uint32_t da = base + adst;
        cp16(da,      sa);      cp16(da + 16, sa + 4);
        cp16(da + 32, sa + 8);  cp16(da + 48, sa + 12);
        const float* sw = wGlob + (size_t)i * 32 * DD;
        const uint32_t dw = base + wdst;
        cp16(dw,      sw);      cp16(dw + 16, sw + 4);
        cp16(dw + 32, sw + 8);  cp16(dw + 48, sw + 12);
        cp_commit();
    };

    const int g = lane >> 2, c = lane & 3;
    const int wm = (wid & 3) * 32, wn = (wid >> 2) * 64;

    float acc[2][8][4];
    #pragma unroll
    for (int mi = 0; mi < 2; mi++)
        #pragma unroll
        for (int nj = 0; nj < 8; nj++)
            #pragma unroll
            for (int q = 0; q < 4; q++) acc[mi][nj][q] = 0.f;

    load_chunk(0);
    load_chunk(1);

    #pragma unroll 1
    for (int i = 0; i < 4; i++) {
        if (i < 2) { asm volatile("cp.async.wait_group 1;" ::: "memory"); }
        else       { asm volatile("cp.async.wait_group 0;" ::: "memory"); }
        __syncthreads();
        if (i < 2) load_chunk(i + 2);

        const float* As = reinterpret_cast<const float*>(sm + 1024 + (i % 3) * STB_ZK);
        const uint32_t* Wu = reinterpret_cast<const uint32_t*>(As + AZ_TB / 4);

        #pragma unroll
        for (int ks = 0; ks < 4; ks++) {
            const int kk = ks * 8 + c;
            uint32_t a0[4], a1[4];
            a0[0] = cvt_tf32(As[(wm + g)      * APAD_ZK + kk]);
            a0[1] = cvt_tf32(As[(wm + g + 8)  * APAD_ZK + kk]);
            a0[2] = cvt_tf32(As[(wm + g)      * APAD_ZK + kk + 4]);
            a0[3] = cvt_tf32(As[(wm + g + 8)  * APAD_ZK + kk + 4]);
            a1[0] = cvt_tf32(As[(wm + 16 + g) * APAD_ZK + kk]);
            a1[1] = cvt_tf32(As[(wm + 24 + g) * APAD_ZK + kk]);
            a1[2] = cvt_tf32(As[(wm + 16 + g) * APAD_ZK + kk + 4]);
            a1[3] = cvt_tf32(As[(wm + 24 + g) * APAD_ZK + kk + 4]);
            #pragma unroll
            for (int nj = 0; nj < 8; nj++) {
                const int col = wn + 8 * nj + g;
                uint32_t b0 = cvt_tf32(__uint_as_float(Wu[kk       * WPAD + col]));
                uint32_t b1 = cvt_tf32(__uint_as_float(Wu[(kk + 4) * WPAD + col]));
                mma_tf32(acc[0][nj], a0[0], a0[1], a0[2], a0[3], b0, b1);
                mma_tf32(acc[1][nj], a1[0], a1[1], a1[2], a1[3], b0, b1);
            }
        }
    }

    __syncthreads();
    __half* hb = reinterpret_cast<__half*>(sm + 1024);
    zpack_store(hb, acc, wm, wn, g, c);
    __syncthreads();

    const int zb = m0 >> 11, mloc = m0 & 2047;
    uint4* dst = reinterpret_cast<uint4*>(Zp + (size_t)zb * NN * DD + (size_t)(mloc >> 5) * 4096);
    const uint4* src = reinterpret_cast<const uint4*>(hb);
    #pragma unroll 1
    for (int i2 = tid; i2 < 2048; i2 += 256)
        dst[i2] = src[i2];
}

// =================================================================
//  fused_rz: x = relu((p0+p1+bias)*invden) (never materialized),
//  then Z = x @ W (whole W in smem), packed-fp16 out. occ 1.
// =================================================================
#define APAD_FZ 132
#define FX_TB (128 * APAD_FZ * 4)             // 67584
#define FW_OFF (1024 + FX_TB)                 // 68608
#define SMEM_FZ (FW_OFF + 128 * WPAD * 4)     // 138240

template<bool FIRST>
__global__ __launch_bounds__(256, 1) void fused_rz(
    const float* __restrict__ part,
    const float* __restrict__ rs,
    float* __restrict__ invd,
    const float* __restrict__ bias,
    const float* __restrict__ W,
    __half* __restrict__ Zp)
{
    extern __shared__ __align__(16) char sm[];
    const uint32_t smb = smem_u32(sm);
    const int tid = threadIdx.x, lane = tid & 31, wid = tid >> 5;
    const int m0 = blockIdx.x * 128;

    {
        const int k = tid >> 1, nh = tid & 1;
        const float* wsrc = W + (size_t)k * DD + nh * 64;
        const uint32_t wdst = smb + FW_OFF + (uint32_t)(k * WPAD + nh * 64) * 4;
        #pragma unroll
        for (int j = 0; j < 16; j++) cp16(wdst + j * 16, wsrc + j * 4);
        cp_commit();
    }

    float* As = reinterpret_cast<float*>(sm + 1024);
    {
        const int tr = tid >> 1, fh = (tid & 1) * 64;
        const size_t tok = (size_t)(m0 + tr);
        float inv;
        if (FIRST) {
            inv = 1.0f / (rs[tok] + 1.0f);
            if ((tid & 1) == 0) invd[tok] = inv;
        } else {
            inv = invd[tok];
        }
        const float4* p0 = reinterpret_cast<const float4*>(part + tok * DD + fh);
        const float4* p1 = reinterpret_cast<const float4*>(part + (size_t)BB * NN * DD + tok * DD + fh);
        #pragma unroll
        for (int j = 0; j < 16; j++) {
            float4 a = p0[j], b2 = p1[j];
            float4 bv = *reinterpret_cast<const float4*>(bias + fh + j * 4);
            float4 o;
            o.x = fmaxf((a.x + b2.x + bv.x) * inv, 0.f);
            o.y = fmaxf((a.y + b2.y + bv.y) * inv, 0.f);
            o.z = fmaxf((a.z + b2.z + bv.z) * inv, 0.f);
            o.w = fmaxf((a.w + b2.w + bv.w) * inv, 0.f);
            *reinterpret_cast<float4*>(As + tr * APAD_FZ + fh + j * 4) = o;
        }
    }
    asm volatile("cp.async.wait_group 0;" ::: "memory");
    __syncthreads();

    const int g = lane >> 2, c = lane & 3;
    const int wm = (wid & 3) * 32, wn = (wid >> 2) * 64;
    const uint32_t* Wu = reinterpret_cast<const uint32_t*>(sm + FW_OFF);

    float acc[2][8][4];
    #pragma unroll
    for (int mi = 0; mi < 2; mi++)
        #pragma unroll
        for (int nj = 0; nj < 8; nj++)
            #pragma unroll
            for (int q = 0; q < 4; q++) acc[mi][nj][q] = 0.f;

    #pragma unroll 1
    for (int ks8 = 0; ks8 < 16; ks8++) {
        const int kk = ks8 * 8 + c;
        uint32_t a0[4], a1[4];
        a0[0] = cvt_tf32(As[(wm + g)      * APAD_FZ + kk]);
        a0[1] = cvt_tf32(As[(wm + g + 8)  * APAD_FZ + kk]);
        a0[2] = cvt_tf32(As[(wm + g)      * APAD_FZ + kk + 4]);
        a0[3] = cvt_tf32(As[(wm + g + 8)  * APAD_FZ + kk + 4]);
        a1[0] = cvt_tf32(As[(wm + 16 + g) * APAD_FZ + kk]);
        a1[1] = cvt_tf32(As[(wm + 24 + g) * APAD_FZ + kk]);
        a1[2] = cvt_tf32(As[(wm + 16 + g) * APAD_FZ + kk + 4]);
        a1[3] = cvt_tf32(As[(wm + 24 + g) * APAD_FZ + kk + 4]);
        #pragma unroll
        for (int nj = 0; nj < 8; nj++) {
            const int col = wn + 8 * nj + g;
            uint32_t b0 = cvt_tf32(__uint_as_float(Wu[kk       * WPAD + col]));
            uint32_t b1 = cvt_tf32(__uint_as_float(Wu[(kk + 4) * WPAD + col]));
            mma_tf32(acc[0][nj], a0[0], a0[1], a0[2], a0[3], b0, b1);
            mma_tf32(acc[1][nj], a1[0], a1[1], a1[2], a1[3], b0, b1);
        }
    }

    __syncthreads();
    __half* hb = reinterpret_cast<__half*>(sm + 1024);
    zpack_store(hb, acc, wm, wn, g, c);
    __syncthreads();

    const int zb = m0 >> 11, mloc = m0 & 2047;
    uint4* dst = reinterpret_cast<uint4*>(Zp + (size_t)zb * NN * DD + (size_t)(mloc >> 5) * 4096);
    const uint4* src = reinterpret_cast<const uint4*>(hb);
    #pragma unroll 1
    for (int i2 = tid; i2 < 2048; i2 += 256)
        dst[i2] = src[i2];
}

// =================================================================
//  Final reduce: out = relu((p0 + p1 + bias) * invden)
// =================================================================
__global__ __launch_bounds__(256, 8) void reduce_fin(
    const float* __restrict__ part,
    const float* __restrict__ bias,
    const float* __restrict__ invd,
    float* __restrict__ out)
{
    const size_t base = ((size_t)blockIdx.x * 256 + threadIdx.x) * 4;
    const int f0 = (int)(base & 127);
    const size_t tg = base >> 7;
    const float inv = invd[tg];

    float4 p0 = *reinterpret_cast<const float4*>(part + base);
    float4 p1 = *reinterpret_cast<const float4*>(part + (size_t)BB * NN * DD + base);
    float4 bv = *reinterpret_cast<const float4*>(bias + f0);
    float4 o;
    o.x = fmaxf((p0.x + p1.x + bv.x) * inv, 0.f);
    o.y = fmaxf((p0.y + p1.y + bv.y) * inv, 0.f);
    o.z = fmaxf((p0.z + p1.z + bv.z) * inv, 0.f);
    o.w = fmaxf((p0.w + p1.w + bv.w) * inv, 0.f);
    *reinterpret_cast<float4*>(out + base) = o;
}

// =================================================================
extern "C" void kernel_launch(void* const* d_in, const int* in_sizes, int n_in,
                              void* d_out, int out_size)
{
    const float *inputs = nullptr, *adj = nullptr, *W = nullptr, *bias = nullptr;
    for (int i = 0; i < n_in; i++) {
        const long long s = in_sizes[i];
        if      (s == (long long)BB * NN * DD) inputs = (const float*)d_in[i];
        else if (s == (long long)BB * NN * NN) adj    = (const float*)d_in[i];
        else if (s == 3LL * DD * DD)           W      = (const float*)d_in[i];
        else if (s == 3LL * DD)                bias   = (const float*)d_in[i];
    }
    float* out = (float*)d_out;

    __half *a16, *zp;
    float *part, *rsv, *invd;
    cudaGetSymbolAddress((void**)&a16,  g_a16);
    cudaGetSymbolAddress((void**)&zp,   g_zpk);
    cudaGetSymbolAddress((void**)&part, g_part);
    cudaGetSymbolAddress((void**)&rsv,  g_rs);
    cudaGetSymbolAddress((void**)&invd, g_invden);

    static bool attr_done = false;
    if (!attr_done) {
        cudaFuncSetAttribute(zk_t,            cudaFuncAttributeMaxDynamicSharedMemorySize, SMEM_ZK);
        cudaFuncSetAttribute(fused_rz<true>,  cudaFuncAttributeMaxDynamicSharedMemorySize, SMEM_FZ);
        cudaFuncSetAttribute(fused_rz<false>, cudaFuncAttributeMaxDynamicSharedMemorySize, SMEM_FZ);
        attr_done = true;
    }

    const dim3 gAX(NN / 128, BB, 2);          // 256 CTAs (split-K x2)
    const dim3 gA2H(NN / 32, BB);             // 512 CTAs
    const int  gZ = (BB * NN) / 128;          // 128 CTAs
    const int  gRED = (BB * NN * DD) / 1024;  // 2048 CTAs

    // layer 0
    zk_t<<<gZ, 256, SMEM_ZK>>>(inputs, W, zp);
    a2h<<<gA2H, 256>>>(adj, a16, rsv);
    ax_direct<<<gAX, 256>>>(a16, zp, part);
    // reduce0 + zk1
    fused_rz<true ><<<gZ, 256, SMEM_FZ>>>(part, rsv, invd, bias, W + DD * DD, zp);
    // layer 1
    ax_direct<<<gAX, 256>>>(a16, zp, part);
    // reduce1 + zk2
    fused_rz<false><<<gZ, 256, SMEM_FZ>>>(part, nullptr, invd, bias + DD, W + 2 * DD * DD, zp);
    // layer 2
    ax_direct<<<gAX, 256>>>(a16, zp, part);
    reduce_fin<<<gRED, 256>>>(part, bias + 2 * DD, invd, out);
}